// round 15
// baseline (speedup 1.0000x reference)
#include <cuda_runtime.h>
#include <cstdint>

#define TAGS       10
#define SEQ        512
#define BATCHN     8192
#define START_TAG  8
#define STOP_TAG   9

#define TBLK       4                        // timesteps per pipeline stage
#define NBLK       (SEQ / TBLK)             // 128 time-blocks
#define STAGES     4
#define EPW        8                        // batch elems per warp (4 lanes each)
#define TSB        (EPW * TAGS * 4)         // 320 B per warp per timestep
#define WPB        4
#define BPB        (EPW * WPB)              // 32 elems per block

// Backpointers: u32 per (t,b); tag n (0..7) argmax nibble at bits 4n. 16.8 MB.
// t=0 never stored / never read (reference discards the t=0 carry).
__device__ unsigned g_bp[(size_t)SEQ * BATCHN];

__device__ __forceinline__ void cp16(uint32_t s, const void* g) {
    asm volatile("cp.async.ca.shared.global [%0], [%1], 16;\n" :: "r"(s), "l"(g));
}
__device__ __forceinline__ void cp_commit() {
    asm volatile("cp.async.commit_group;\n" ::: "memory");
}
__device__ __forceinline__ void cp_wait2() {
    asm volatile("cp.async.wait_group 2;\n" ::: "memory");
}

// tournament node, tie -> left (first index); exact compares
#define TOURN(vl, il, vr, ir, mo, io) \
    { bool _p = (vr) > (vl); mo = _p ? (vr) : (vl); io = _p ? (ir) : (il); }
// node with runtime tie-direction: tie -> right iff tb (restores absolute
// first-index order under the XOR-permutation); exact compares
#define TOURNX(vl, il, vr, ir, tb, mo, io)                                 \
    { bool _p = ((vr) > (vl)) || ((tb) && ((vr) == (vl)));                 \
      mo = _p ? (vr) : (vl); io = _p ? (ir) : (il); }

__global__ __launch_bounds__(128, 1)
void crf_viterbi15(const float* __restrict__ feats,
                   const float* __restrict__ trans,
                   float* __restrict__ out) {
    // warp-private rings: 4 warps x 4 stages x (4 ts x 320 B) = 20 KB
    __shared__ __align__(16) char ring[WPB][STAGES][TBLK * TSB];

    const int tid  = threadIdx.x;
    const int warp = tid >> 5;
    const int lane = tid & 31;
    const int e    = lane >> 2;          // element within warp (0..7)
    const int h    = lane & 3;           // lane owns abs tags 2h, 2h+1
    const int m    = 2 * h;              // XOR permutation mask (even)
    const bool tie1 = (h & 1) != 0;      // tree level-1 tie direction (bit1 of m)
    const bool tie2 = (h & 2) != 0;      // tree level-2 tie direction (bit2 of m)
    const int b    = blockIdx.x * BPB + warp * EPW + e;

    const char*  gbase = (const char*)feats +
                         ((size_t)blockIdx.x * BPB + (size_t)warp * EPW) * (TAGS * 4);
    const size_t gstep = (size_t)BATCHN * TAGS * 4;
    const bool cp_lane = (lane < 20);    // 20 x 16B chunks per timestep

    uint32_t s_ring0;
    asm("{ .reg .u64 t; cvta.to.shared.u64 t, %1; cvt.u32.u64 %0, t; }"
        : "=r"(s_ring0) : "l"(&ring[warp][0][0]));

    // permuted transitions: Tm[i][p] = trans[i^m][p^m]; Tc[i] = trans[i^m][START]
    float Tm[8][8], Tc[8];
#pragma unroll
    for (int i = 0; i < 8; i++) {
        const int ri = i ^ m;
#pragma unroll
        for (int p = 0; p < 8; p++)
            Tm[i][p] = __ldg(trans + ri * TAGS + (p ^ m));
        Tc[i] = __ldg(trans + ri * TAGS + START_TAG);
    }

    // prologue: fill stages 0..2 (one commit group per time-block)
#pragma unroll
    for (int s = 0; s < STAGES - 1; s++) {
        uint32_t sb = s_ring0 + s * (TBLK * TSB);
#pragma unroll
        for (int k = 0; k < TBLK; k++) {
            const char* g = gbase + (size_t)(s * TBLK + k) * gstep;
            if (cp_lane) cp16(sb + k * TSB + lane * 16, g + lane * 16);
        }
        cp_commit();
    }

    // feat LDS offsets: permuted pair k lives at abs pair k^h (8B aligned)
    const int o0 = e * 40 + ((0 ^ h) << 3);
    const int o1 = e * 40 + ((1 ^ h) << 3);
    const int o2 = e * 40 + ((2 ^ h) << 3);
    const int o3 = e * 40 + ((3 ^ h) << 3);

    // bp byte pointer: byte h of u32 record (t*BATCHN + b)
    char* pbp = (char*)g_bp + 4 * ((size_t)b) + h;
    const unsigned xm8 = (unsigned)(m * 0x11);   // perm->abs nibble fix

    float fv[8];          // state in PERMUTED coordinates

    for (int ib = 0; ib < NBLK; ib++) {
        cp_wait2();
        __syncwarp();

        const char* sp = ring[warp][ib & (STAGES - 1)];

        // prefetch time-block ib+3 into the freed stage; always commit
        {
            const int nb = ib + STAGES - 1;
            if (nb < NBLK) {
                uint32_t sb = s_ring0 + (nb & (STAGES - 1)) * (TBLK * TSB);
#pragma unroll
                for (int k = 0; k < TBLK; k++) {
                    const char* g = gbase + (size_t)(nb * TBLK + k) * gstep;
                    if (cp_lane) cp16(sb + k * TSB + lane * 16, g + lane * 16);
                }
            }
            cp_commit();
        }

#pragma unroll
        for (int k = 0; k < TBLK; k++) {
            const int t = ib * TBLK + k;
            const char* sk = sp + k * TSB;
            float2 p0 = *(const float2*)(sk + o0);
            float2 p1 = *(const float2*)(sk + o1);
            float2 p2 = *(const float2*)(sk + o2);
            float2 p3 = *(const float2*)(sk + o3);
            float f[8] = { p0.x, p0.y, p1.x, p1.y, p2.x, p2.y, p3.x, p3.y };

            if (ib == 0 && k == 0) {
                // exact peeled t=0: winner prev is START for every tag
#pragma unroll
                for (int i = 0; i < 8; i++) fv[i] = Tc[i] + f[i];
                pbp += 4 * (size_t)BATCHN;   // FIX: skip t=0 record (never read)
                continue;
            }

            float nf[8];
            unsigned bits = 0u;
            // owned tags = permuted rows 0,1 (abs 2h, 2h+1): full tournaments
#pragma unroll
            for (int i = 0; i < 2; i++) {
                float v0 = fv[0] + Tm[i][0], v1 = fv[1] + Tm[i][1];
                float v2 = fv[2] + Tm[i][2], v3 = fv[3] + Tm[i][3];
                float v4 = fv[4] + Tm[i][4], v5 = fv[5] + Tm[i][5];
                float v6 = fv[6] + Tm[i][6], v7 = fv[7] + Tm[i][7];
                float a0, a1, a2, a3, c0, c1, mx;
                int   j0, j1, j2, j3, q0, q1, bi;
                TOURN (v0, 0, v1, 1, a0, j0);            // level 0: bit0 of m = 0
                TOURN (v2, 2, v3, 3, a1, j1);
                TOURN (v4, 4, v5, 5, a2, j2);
                TOURN (v6, 6, v7, 7, a3, j3);
                TOURNX(a0, j0, a1, j1, tie1, c0, q0);    // level 1: bit1 of m
                TOURNX(a2, j2, a3, j3, tie1, c1, q1);
                TOURNX(c0, q0, c1, q1, tie2, mx, bi);    // level 2: bit2 of m
                nf[i] = mx + f[i];
                bits |= (unsigned)bi << (4 * i);
            }
            // foreign tags = permuted rows 2..7: value-only fmax trees
#pragma unroll
            for (int i = 2; i < 8; i++) {
                float v0 = fv[0] + Tm[i][0], v1 = fv[1] + Tm[i][1];
                float v2 = fv[2] + Tm[i][2], v3 = fv[3] + Tm[i][3];
                float v4 = fv[4] + Tm[i][4], v5 = fv[5] + Tm[i][5];
                float v6 = fv[6] + Tm[i][6], v7 = fv[7] + Tm[i][7];
                float mx = fmaxf(fmaxf(fmaxf(v0, v1), fmaxf(v2, v3)),
                                 fmaxf(fmaxf(v4, v5), fmaxf(v6, v7)));
                nf[i] = mx + f[i];
            }
#pragma unroll
            for (int i = 0; i < 8; i++) fv[i] = nf[i];

            // my byte: abs nibbles of tags 2h, 2h+1
            *pbp = (char)((bits ^ xm8) & 0xFF);
            pbp += 4 * (size_t)BATCHN;
        }
    }

    // terminal + backtrace on h==0 lanes (identity permutation)
    if (h == 0) {
        float tv[8];
#pragma unroll
        for (int i = 0; i < 8; i++)
            tv[i] = fv[i] + __ldg(trans + STOP_TAG * TAGS + i);
        float a0, a1, a2, a3, c0, c1, mx;
        int   j0, j1, j2, j3, q0, q1, tag;
        TOURN(tv[0], 0, tv[1], 1, a0, j0);
        TOURN(tv[2], 2, tv[3], 3, a1, j1);
        TOURN(tv[4], 4, tv[5], 5, a2, j2);
        TOURN(tv[6], 6, tv[7], 7, a3, j3);
        TOURN(a0, j0, a1, j1, c0, q0);
        TOURN(a2, j2, a3, j3, c1, q1);
        TOURN(c0, q0, c1, q1, mx, tag);

        out[b] = mx;
        float* __restrict__ path = out + BATCHN;
        const unsigned* __restrict__ rec = g_bp + b;
#pragma unroll 16
        for (int t = SEQ - 1; t >= 1; t--) {
            path[(size_t)t * BATCHN + b] = (float)tag;
            const unsigned w = rec[(size_t)t * BATCHN];
            tag = (int)((w >> (4 * tag)) & 0xFu);
        }
        path[b] = (float)tag;
    }
}

extern "C" void kernel_launch(void* const* d_in, const int* in_sizes, int n_in,
                              void* d_out, int out_size) {
    const float* feats = (const float*)d_in[0];
    const float* trans = (const float*)d_in[1];
    float* out = (float*)d_out;

    // 256 blocks x 128 threads = 1024 warps (~1.73/SMSP), zero per-step comm
    crf_viterbi15<<<BATCHN / BPB, 128>>>(feats, trans, out);
}

// round 16
// speedup vs baseline: 1.1507x; 1.1507x over previous
#include <cuda_runtime.h>
#include <cstdint>

#define TAGS       10
#define SEQ        512
#define BATCHN     8192
#define START_TAG  8
#define STOP_TAG   9

#define TBLK       4                        // timesteps per pipeline stage
#define NBLK       (SEQ / TBLK)             // 128 time-blocks
#define STAGES     4
#define EPW        14                       // batch elems per warp (2 lanes each)
#define TSB        (EPW * TAGS * 4)         // 560 B per warp per timestep
#define WPB        4
#define BPB        (EPW * WPB)              // 56 elems per block
#define GRID       ((BATCHN + BPB - 1) / BPB)   // 147 blocks -> 147 SMs busy

// Backpointers: u32 per (t,b); tag n (0..7) argmax nibble at bits 4n. 16.8 MB.
// t=0 never stored / never read (reference discards the t=0 carry).
__device__ unsigned g_bp[(size_t)SEQ * BATCHN];

typedef unsigned long long u64;

__device__ __forceinline__ void cp16(uint32_t s, const void* g) {
    asm volatile("cp.async.ca.shared.global [%0], [%1], 16;\n" :: "r"(s), "l"(g));
}
__device__ __forceinline__ void cp_commit() {
    asm volatile("cp.async.commit_group;\n" ::: "memory");
}
__device__ __forceinline__ void cp_wait2() {
    asm volatile("cp.async.wait_group 2;\n" ::: "memory");
}

// packed f32x2 helpers (round-nearest -> bitwise identical to scalar FADD)
__device__ __forceinline__ u64 pk(float lo, float hi) {
    u64 r; asm("mov.b64 %0, {%1, %2};" : "=l"(r) : "f"(lo), "f"(hi)); return r;
}
__device__ __forceinline__ void upk(float& lo, float& hi, u64 v) {
    asm("mov.b64 {%0, %1}, %2;" : "=f"(lo), "=f"(hi) : "l"(v));
}
__device__ __forceinline__ u64 addx2(u64 a, u64 b) {
    u64 r; asm("add.rn.f32x2 %0, %1, %2;" : "=l"(r) : "l"(a), "l"(b)); return r;
}

// tournament node, tie -> left (first index); exact compares
#define TOURN(vl, il, vr, ir, mo, io) \
    { bool _p = (vr) > (vl); mo = _p ? (vr) : (vl); io = _p ? (ir) : (il); }
// final-level node: tie -> right iff hb (restores absolute first-index order
// under the half-swap permutation); exact compares
#define TOURNF(vl, il, vr, ir, hb, mo, io)                                 \
    { bool _p = ((vr) > (vl)) || (((vr) == (vl)) && (hb));                 \
      mo = _p ? (vr) : (vl); io = _p ? (ir) : (il); }

__global__ __launch_bounds__(128, 1)
void crf_viterbi16(const float* __restrict__ feats,
                   const float* __restrict__ trans,
                   float* __restrict__ out) {
    // warp-private rings: 4 warps x 4 stages x (4 ts x 560 B) = 35840 B
    __shared__ __align__(16) char ring[WPB][STAGES][TBLK * TSB];

    const int tid  = threadIdx.x;
    const int warp = tid >> 5;
    const int lane = tid & 31;
    int e          = lane >> 1;          // local elem 0..15
    const bool live = (e < EPW);         // lanes 28-31 mirror elem 13
    if (!live) e = EPW - 1;
    const int h    = lane & 1;           // half-swap: lane owns abs tags 4h..4h+3
    const bool hb  = (h != 0);

    int base_b = blockIdx.x * BPB;
    if (base_b > BATCHN - BPB) base_b = BATCHN - BPB;   // tail overlaps (benign)
    const int b = base_b + warp * EPW + e;

    // warp slice base: base_b*40 and warp*560 are multiples of 16 -> cp16 safe
    const char*  gbase = (const char*)feats +
                         (size_t)base_b * (TAGS * 4) + (size_t)warp * TSB;
    const size_t gstep = (size_t)BATCHN * TAGS * 4;

    uint32_t s_ring0;
    asm("{ .reg .u64 t; cvta.to.shared.u64 t, %1; cvt.u32.u64 %0, t; }"
        : "=r"(s_ring0) : "l"(&ring[warp][0][0]));

    // permuted transitions, PACKED by prev-pairs: row/col r = (x + 4h) & 7
    // Tp[i][k] = {trans[ri][(2k)^perm], trans[ri][(2k+1)^perm]}
    u64 Tp[8][4];
    u64 TcP[4];
    {
        float Tc[8];
#pragma unroll
        for (int i = 0; i < 8; i++) {
            const int ri = (i + 4 * h) & 7;
#pragma unroll
            for (int k = 0; k < 4; k++) {
                const float lo = __ldg(trans + ri * TAGS + ((2 * k + 4 * h) & 7));
                const float hi = __ldg(trans + ri * TAGS + ((2 * k + 1 + 4 * h) & 7));
                Tp[i][k] = pk(lo, hi);
            }
            Tc[i] = __ldg(trans + ri * TAGS + START_TAG);
        }
#pragma unroll
        for (int k = 0; k < 4; k++) TcP[k] = pk(Tc[2 * k], Tc[2 * k + 1]);
    }

    // prologue: fill stages 0..2 (35 x 16B chunks per ts; one commit per block)
#pragma unroll
    for (int s = 0; s < STAGES - 1; s++) {
        uint32_t sb = s_ring0 + s * (TBLK * TSB);
#pragma unroll
        for (int k = 0; k < TBLK; k++) {
            const char* g = gbase + (size_t)(s * TBLK + k) * gstep;
            cp16(sb + k * TSB + lane * 16, g + lane * 16);
            if (lane < 3) cp16(sb + k * TSB + 512 + lane * 16, g + 512 + lane * 16);
        }
        cp_commit();
    }

    // feat LDS offsets: h swaps the two 16B halves so f[] is in permuted order
    const int offA = e * 40 + (h ? 16 : 0);   // perm tags 0..3
    const int offB = e * 40 + (h ? 0 : 16);   // perm tags 4..7

    unsigned short* __restrict__ bp16 = (unsigned short*)g_bp;
    const unsigned xmask = h ? 0x4444u : 0u;  // perm->abs nibble fix

    u64 FV[4];          // packed state {fv[2k], fv[2k+1]} in PERMUTED coords

    for (int ib = 0; ib < NBLK; ib++) {
        cp_wait2();
        __syncwarp();

        const char* sp = ring[warp][ib & (STAGES - 1)];

        // prefetch time-block ib+3 into the freed stage; always commit
        {
            const int nb = ib + STAGES - 1;
            if (nb < NBLK) {
                uint32_t sb = s_ring0 + (nb & (STAGES - 1)) * (TBLK * TSB);
#pragma unroll
                for (int k = 0; k < TBLK; k++) {
                    const char* g = gbase + (size_t)(nb * TBLK + k) * gstep;
                    cp16(sb + k * TSB + lane * 16, g + lane * 16);
                    if (lane < 3)
                        cp16(sb + k * TSB + 512 + lane * 16, g + 512 + lane * 16);
                }
            }
            cp_commit();
        }

#pragma unroll
        for (int k = 0; k < TBLK; k++) {
            const int t = ib * TBLK + k;
            const char* sk = sp + k * TSB;
            float2 p0 = *(const float2*)(sk + offA);
            float2 p1 = *(const float2*)(sk + offA + 8);
            float2 p2 = *(const float2*)(sk + offB);
            float2 p3 = *(const float2*)(sk + offB + 8);
            float f[8] = { p0.x, p0.y, p1.x, p1.y, p2.x, p2.y, p3.x, p3.y };

            if (ib == 0 && k == 0) {
                // exact peeled t=0: winner prev is START for every tag
                FV[0] = addx2(TcP[0], pk(f[0], f[1]));
                FV[1] = addx2(TcP[1], pk(f[2], f[3]));
                FV[2] = addx2(TcP[2], pk(f[4], f[5]));
                FV[3] = addx2(TcP[3], pk(f[6], f[7]));
                continue;   // t=0 record never read
            }

            float nf[8];
            unsigned bits = 0u;
            // owned tags = permuted rows 0..3: full max+argmax tournaments
#pragma unroll
            for (int i = 0; i < 4; i++) {
                u64 V0 = addx2(FV[0], Tp[i][0]);
                u64 V1 = addx2(FV[1], Tp[i][1]);
                u64 V2 = addx2(FV[2], Tp[i][2]);
                u64 V3 = addx2(FV[3], Tp[i][3]);
                float v0, v1, v2, v3, v4, v5, v6, v7;
                upk(v0, v1, V0); upk(v2, v3, V1);
                upk(v4, v5, V2); upk(v6, v7, V3);
                float a0, a1, a2, a3, c0, c1, mx;
                int   j0, j1, j2, j3, q0, q1, bi;
                TOURN (v0, 0, v1, 1, a0, j0);
                TOURN (v2, 2, v3, 3, a1, j1);
                TOURN (v4, 4, v5, 5, a2, j2);
                TOURN (v6, 6, v7, 7, a3, j3);
                TOURN (a0, j0, a1, j1, c0, q0);
                TOURN (a2, j2, a3, j3, c1, q1);
                TOURNF(c0, q0, c1, q1, hb, mx, bi);   // abs-order tie-break
                nf[i] = mx + f[i];
                bits |= (unsigned)bi << (4 * i);
            }
            // foreign tags = permuted rows 4..7: value-only fmax trees
#pragma unroll
            for (int i = 4; i < 8; i++) {
                u64 V0 = addx2(FV[0], Tp[i][0]);
                u64 V1 = addx2(FV[1], Tp[i][1]);
                u64 V2 = addx2(FV[2], Tp[i][2]);
                u64 V3 = addx2(FV[3], Tp[i][3]);
                float v0, v1, v2, v3, v4, v5, v6, v7;
                upk(v0, v1, V0); upk(v2, v3, V1);
                upk(v4, v5, V2); upk(v6, v7, V3);
                float mx = fmaxf(fmaxf(fmaxf(v0, v1), fmaxf(v2, v3)),
                                 fmaxf(fmaxf(v4, v5), fmaxf(v6, v7)));
                nf[i] = mx + f[i];
            }
            FV[0] = pk(nf[0], nf[1]); FV[1] = pk(nf[2], nf[3]);
            FV[2] = pk(nf[4], nf[5]); FV[3] = pk(nf[6], nf[7]);

            // my u16: abs nibbles of tags 4h..4h+3
            if (live)
                bp16[2 * ((size_t)t * BATCHN + b) + h] =
                    (unsigned short)(bits ^ xmask);
        }
    }

    // terminal + backtrace on live h==0 lanes (identity permutation)
    if (!hb && live) {
        float fv[8];
        upk(fv[0], fv[1], FV[0]); upk(fv[2], fv[3], FV[1]);
        upk(fv[4], fv[5], FV[2]); upk(fv[6], fv[7], FV[3]);
        float tv[8];
#pragma unroll
        for (int i = 0; i < 8; i++)
            tv[i] = fv[i] + __ldg(trans + STOP_TAG * TAGS + i);
        float a0, a1, a2, a3, c0, c1, mx;
        int   j0, j1, j2, j3, q0, q1, tag;
        TOURN(tv[0], 0, tv[1], 1, a0, j0);
        TOURN(tv[2], 2, tv[3], 3, a1, j1);
        TOURN(tv[4], 4, tv[5], 5, a2, j2);
        TOURN(tv[6], 6, tv[7], 7, a3, j3);
        TOURN(a0, j0, a1, j1, c0, q0);
        TOURN(a2, j2, a3, j3, c1, q1);
        TOURN(c0, q0, c1, q1, mx, tag);

        out[b] = mx;
        float* __restrict__ path = out + BATCHN;
        const unsigned* __restrict__ rec = g_bp + b;
#pragma unroll 16
        for (int t = SEQ - 1; t >= 1; t--) {
            path[(size_t)t * BATCHN + b] = (float)tag;
            const unsigned w = rec[(size_t)t * BATCHN];
            tag = (int)((w >> (4 * tag)) & 0xFu);
        }
        path[b] = (float)tag;
    }
}

extern "C" void kernel_launch(void* const* d_in, const int* in_sizes, int n_in,
                              void* d_out, int out_size) {
    const float* feats = (const float*)d_in[0];
    const float* trans = (const float*)d_in[1];
    float* out = (float*)d_out;

    // 147 blocks x 128 threads: full-chip spread, 2 lanes/element, no comm
    crf_viterbi16<<<GRID, 128>>>(feats, trans, out);
}